// round 2
// baseline (speedup 1.0000x reference)
#include <cuda_runtime.h>

#define NPERSEG 1024
#define STEP     256
#define SEQ    16384
#define NWIN      61
#define BATCH   1024
#define THREADS  256

// Interleaved weights: g_w[2*i] = re weights for samples 4i..4i+3,
//                      g_w[2*i+1] = im weights. 32B contiguous per index i.
__device__ float4 g_w[2 * (SEQ / 4)];

__global__ void build_weights_kernel(const float* __restrict__ freqs) {
    int s = blockIdx.x * blockDim.x + threadIdx.x;   // sample index
    if (s >= SEQ) return;
    const float TWO_PI = 6.283185307179586476925f;
    float wre = 0.f, wim = 0.f;
    int pbase = s & (STEP - 1);
    #pragma unroll
    for (int k = 0; k < 4; ++k) {
        int p = pbase + k * STEP;
        int w = (s - p) >> 8;
        if (w >= 0 && w < NWIN) {
            float ang = TWO_PI * freqs[p];
            float sn, cs;
            sincosf(ang, &sn, &cs);
            wre += cs;
            wim -= sn;
        }
    }
    const float inv = 1.0f / (float)NWIN;
    float* wf = (float*)g_w;
    int i = s >> 2;        // float4 index
    int c = s & 3;         // component
    wf[(2 * i) * 4 + c]     = wre * inv;
    wf[(2 * i + 1) * 4 + c] = wim * inv;
}

__global__ __launch_bounds__(THREADS) void welch_reduce_kernel(
    const float4* __restrict__ in,
    const float*  __restrict__ fc_w,
    const float*  __restrict__ fc_b,
    float*        __restrict__ out)
{
    const int b = blockIdx.x;
    const float4* __restrict__ row = in + (size_t)b * (SEQ / 4);

    // 4 independent accumulator pairs; 16 iterations grouped 4-at-a-time.
    float re0 = 0.f, re1 = 0.f, re2 = 0.f, re3 = 0.f;
    float im0 = 0.f, im1 = 0.f, im2 = 0.f, im3 = 0.f;

    #pragma unroll
    for (int base = 0; base < SEQ / 4; base += 4 * THREADS) {
        const int i0 = base + threadIdx.x;
        const int i1 = i0 + THREADS;
        const int i2 = i0 + 2 * THREADS;
        const int i3 = i0 + 3 * THREADS;

        // Batch all loads first: input streams L2-only (.cg), weights stay in L1.
        float4 x0 = __ldcg(&row[i0]);
        float4 x1 = __ldcg(&row[i1]);
        float4 x2 = __ldcg(&row[i2]);
        float4 x3 = __ldcg(&row[i3]);
        float4 c0 = g_w[2 * i0],     d0 = g_w[2 * i0 + 1];
        float4 c1 = g_w[2 * i1],     d1 = g_w[2 * i1 + 1];
        float4 c2 = g_w[2 * i2],     d2 = g_w[2 * i2 + 1];
        float4 c3 = g_w[2 * i3],     d3 = g_w[2 * i3 + 1];

        re0 = fmaf(x0.x, c0.x, re0); re0 = fmaf(x0.y, c0.y, re0);
        re0 = fmaf(x0.z, c0.z, re0); re0 = fmaf(x0.w, c0.w, re0);
        im0 = fmaf(x0.x, d0.x, im0); im0 = fmaf(x0.y, d0.y, im0);
        im0 = fmaf(x0.z, d0.z, im0); im0 = fmaf(x0.w, d0.w, im0);

        re1 = fmaf(x1.x, c1.x, re1); re1 = fmaf(x1.y, c1.y, re1);
        re1 = fmaf(x1.z, c1.z, re1); re1 = fmaf(x1.w, c1.w, re1);
        im1 = fmaf(x1.x, d1.x, im1); im1 = fmaf(x1.y, d1.y, im1);
        im1 = fmaf(x1.z, d1.z, im1); im1 = fmaf(x1.w, d1.w, im1);

        re2 = fmaf(x2.x, c2.x, re2); re2 = fmaf(x2.y, c2.y, re2);
        re2 = fmaf(x2.z, c2.z, re2); re2 = fmaf(x2.w, c2.w, re2);
        im2 = fmaf(x2.x, d2.x, im2); im2 = fmaf(x2.y, d2.y, im2);
        im2 = fmaf(x2.z, d2.z, im2); im2 = fmaf(x2.w, d2.w, im2);

        re3 = fmaf(x3.x, c3.x, re3); re3 = fmaf(x3.y, c3.y, re3);
        re3 = fmaf(x3.z, c3.z, re3); re3 = fmaf(x3.w, c3.w, re3);
        im3 = fmaf(x3.x, d3.x, im3); im3 = fmaf(x3.y, d3.y, im3);
        im3 = fmaf(x3.z, d3.z, im3); im3 = fmaf(x3.w, d3.w, im3);
    }

    float re = (re0 + re1) + (re2 + re3);
    float im = (im0 + im1) + (im2 + im3);

    #pragma unroll
    for (int off = 16; off > 0; off >>= 1) {
        re += __shfl_xor_sync(0xffffffffu, re, off);
        im += __shfl_xor_sync(0xffffffffu, im, off);
    }

    __shared__ float sre[THREADS / 32];
    __shared__ float sim[THREADS / 32];
    const int warp = threadIdx.x >> 5;
    const int lane = threadIdx.x & 31;
    if (lane == 0) { sre[warp] = re; sim[warp] = im; }
    __syncthreads();

    if (threadIdx.x == 0) {
        float fr = 0.f, fi = 0.f;
        #pragma unroll
        for (int w = 0; w < THREADS / 32; ++w) { fr += sre[w]; fi += sim[w]; }
        float psd = fr * fr + fi * fi;
        out[b] = fmaf(psd, fc_w[0], fc_b[0]);
    }
}

extern "C" void kernel_launch(void* const* d_in, const int* in_sizes, int n_in,
                              void* d_out, int out_size) {
    const float* input = (const float*)d_in[0];   // (1024, 16384) f32
    const float* freqs = (const float*)d_in[1];   // (1024,) f32
    const float* fc_w  = (const float*)d_in[2];   // (1,1) f32
    const float* fc_b  = (const float*)d_in[3];   // (1,) f32
    float* out = (float*)d_out;                   // (1024, 1) f32

    build_weights_kernel<<<SEQ / THREADS, THREADS>>>(freqs);
    welch_reduce_kernel<<<BATCH, THREADS>>>((const float4*)input, fc_w, fc_b, out);
}

// round 3
// speedup vs baseline: 1.4536x; 1.4536x over previous
#include <cuda_runtime.h>

#define NPERSEG 1024
#define STEP     256
#define SEQ    16384
#define NWIN      61
#define BATCH   1024
#define THREADS  256

#define CTILE   2048                 // samples per column block
#define CF4     (CTILE / 4)          // 512 float4 per column block
#define RTILE   8                    // rows per CTA
#define NCB     (SEQ / CTILE)        // 8 column blocks
#define NRB     (BATCH / RTILE)      // 128 row blocks

// Interleaved weights: g_w[2*i] = re weights for samples 4i..4i+3,
//                      g_w[2*i+1] = im weights.
__device__ float4 g_w[2 * (SEQ / 4)];
// Per-(row, col-block) partial sums (re, im). Written exactly once per slot.
__device__ float2 g_part[BATCH * NCB];

__global__ void build_weights_kernel(const float* __restrict__ freqs) {
    int s = blockIdx.x * blockDim.x + threadIdx.x;
    if (s >= SEQ) return;
    const float TWO_PI = 6.283185307179586476925f;
    float wre = 0.f, wim = 0.f;
    int pbase = s & (STEP - 1);
    #pragma unroll
    for (int k = 0; k < 4; ++k) {
        int p = pbase + k * STEP;
        int w = (s - p) >> 8;
        if (w >= 0 && w < NWIN) {
            float ang = TWO_PI * freqs[p];
            float sn, cs;
            sincosf(ang, &sn, &cs);
            wre += cs;
            wim -= sn;
        }
    }
    const float inv = 1.0f / (float)NWIN;
    float* wf = (float*)g_w;
    int i = s >> 2;
    int c = s & 3;
    wf[(2 * i) * 4 + c]     = wre * inv;
    wf[(2 * i + 1) * 4 + c] = wim * inv;
}

// Main kernel: CTA (cb, rb) handles rows [rb*8, rb*8+8) x cols [cb*2048, +2048).
// Weights staged in smem; 8 independent row-loads per column group give MLP=8
// per thread structurally.
__global__ __launch_bounds__(THREADS) void welch_main_kernel(
    const float4* __restrict__ in)
{
    __shared__ float4 sw[2 * CF4];   // 16 KB, reused as reduce buffer after loop

    const int cb  = blockIdx.x;
    const int rb  = blockIdx.y;
    const int tid = threadIdx.x;

    // Stage this column block's weights (interleaved re/im float4 pairs).
    #pragma unroll
    for (int j = 0; j < (2 * CF4) / THREADS; ++j)
        sw[tid + j * THREADS] = g_w[cb * (2 * CF4) + tid + j * THREADS];
    __syncthreads();

    const int row0 = rb * RTILE;
    const float4* __restrict__ base =
        in + (size_t)row0 * (SEQ / 4) + cb * CF4;

    float accre[RTILE], accim[RTILE];
    #pragma unroll
    for (int r = 0; r < RTILE; ++r) { accre[r] = 0.f; accim[r] = 0.f; }

    #pragma unroll
    for (int g = 0; g < CF4 / THREADS; ++g) {
        const int l = g * THREADS + tid;
        const float4 cr = sw[2 * l];
        const float4 ci = sw[2 * l + 1];

        float4 x[RTILE];
        #pragma unroll
        for (int r = 0; r < RTILE; ++r)
            x[r] = __ldcg(base + (size_t)r * (SEQ / 4) + l);

        #pragma unroll
        for (int r = 0; r < RTILE; ++r) {
            accre[r] = fmaf(x[r].x, cr.x, accre[r]);
            accre[r] = fmaf(x[r].y, cr.y, accre[r]);
            accre[r] = fmaf(x[r].z, cr.z, accre[r]);
            accre[r] = fmaf(x[r].w, cr.w, accre[r]);
            accim[r] = fmaf(x[r].x, ci.x, accim[r]);
            accim[r] = fmaf(x[r].y, ci.y, accim[r]);
            accim[r] = fmaf(x[r].z, ci.z, accim[r]);
            accim[r] = fmaf(x[r].w, ci.w, accim[r]);
        }
    }

    // Block reduce per row, reusing sw as scratch (all weight reads are done).
    __syncthreads();
    float* sre = (float*)sw;               // RTILE*256 floats = 8 KB
    float* sim = sre + RTILE * THREADS;    // another 8 KB
    #pragma unroll
    for (int r = 0; r < RTILE; ++r) {
        sre[r * THREADS + tid] = accre[r];
        sim[r * THREADS + tid] = accim[r];
    }
    __syncthreads();

    // Warp w reduces row w (RTILE == warps per CTA == 8).
    const int w    = tid >> 5;
    const int lane = tid & 31;
    float vre = 0.f, vim = 0.f;
    #pragma unroll
    for (int k = 0; k < THREADS / 32; ++k) {
        vre += sre[w * THREADS + k * 32 + lane];
        vim += sim[w * THREADS + k * 32 + lane];
    }
    #pragma unroll
    for (int off = 16; off > 0; off >>= 1) {
        vre += __shfl_xor_sync(0xffffffffu, vre, off);
        vim += __shfl_xor_sync(0xffffffffu, vim, off);
    }
    if (lane == 0)
        g_part[(row0 + w) * NCB + cb] = make_float2(vre, vim);
}

__global__ void epilogue_kernel(const float* __restrict__ fc_w,
                                const float* __restrict__ fc_b,
                                float* __restrict__ out)
{
    int b = blockIdx.x * blockDim.x + threadIdx.x;
    if (b >= BATCH) return;
    float fr = 0.f, fi = 0.f;
    #pragma unroll
    for (int c = 0; c < NCB; ++c) {
        float2 p = g_part[b * NCB + c];
        fr += p.x;
        fi += p.y;
    }
    float psd = fr * fr + fi * fi;
    out[b] = fmaf(psd, fc_w[0], fc_b[0]);
}

extern "C" void kernel_launch(void* const* d_in, const int* in_sizes, int n_in,
                              void* d_out, int out_size) {
    const float* input = (const float*)d_in[0];   // (1024, 16384) f32
    const float* freqs = (const float*)d_in[1];   // (1024,) f32
    const float* fc_w  = (const float*)d_in[2];   // (1,1) f32
    const float* fc_b  = (const float*)d_in[3];   // (1,) f32
    float* out = (float*)d_out;                   // (1024, 1) f32

    build_weights_kernel<<<SEQ / THREADS, THREADS>>>(freqs);
    welch_main_kernel<<<dim3(NCB, NRB), THREADS>>>((const float4*)input);
    epilogue_kernel<<<(BATCH + THREADS - 1) / THREADS, THREADS>>>(fc_w, fc_b, out);
}